// round 10
// baseline (speedup 1.0000x reference)
#include <cuda_runtime.h>
#include <cuda_bf16.h>
#include <cstdint>

#define MULV    128
#define NZ_COLS 512
#define PW_SS 0.0625f
#define PW_VV 0.03608439182435161f
#define PW_SV 0.0078125f
#define K2_ZT 32

// Transposed tf32-rounded weights: g_wt[v][w][u] fp32 (8.4 MB)
__device__ float g_wt[128 * 128 * 128];

// ---------------- helpers ----------------
__device__ __forceinline__ uint32_t smem_u32(const void* p) {
    uint32_t a;
    asm("{ .reg .u64 t; cvta.to.shared.u64 t, %1; cvt.u32.u64 %0, t; }" : "=r"(a) : "l"(p));
    return a;
}
__device__ __forceinline__ void ldsm4(uint32_t r[4], uint32_t addr) {
    asm volatile("ldmatrix.sync.aligned.m8n8.x4.shared.b16 {%0,%1,%2,%3}, [%4];"
                 : "=r"(r[0]), "=r"(r[1]), "=r"(r[2]), "=r"(r[3]) : "r"(addr));
}
__device__ __forceinline__ void mma_tf32(float c[4], const uint32_t a[4],
                                         uint32_t b0, uint32_t b1) {
    asm volatile("mma.sync.aligned.m16n8k8.row.col.f32.tf32.tf32.f32 "
                 "{%0,%1,%2,%3}, {%4,%5,%6,%7}, {%8,%9}, {%0,%1,%2,%3};"
                 : "+f"(c[0]), "+f"(c[1]), "+f"(c[2]), "+f"(c[3])
                 : "r"(a[0]), "r"(a[1]), "r"(a[2]), "r"(a[3]), "r"(b0), "r"(b1));
}
__device__ __forceinline__ void cp16(uint32_t sdst, const void* gsrc) {
    asm volatile("cp.async.cg.shared.global [%0], [%1], 16;" :: "r"(sdst), "l"(gsrc));
}
__device__ __forceinline__ void cp_commit() { asm volatile("cp.async.commit_group;"); }
template <int N> __device__ __forceinline__ void cp_wait() {
    asm volatile("cp.async.wait_group %0;" :: "n"(N));
}
__device__ __forceinline__ uint32_t tf32r(float f) {
    uint32_t o;
    asm("cvt.rna.tf32.f32 %0, %1;" : "=r"(o) : "f"(f));
    return o;
}

// ---------------------------------------------------------------------------
// Pack: g_wt[v][w][u] = tf32_round(w_sv[u][v][w]). One block per v.
// ---------------------------------------------------------------------------
__global__ void pack_b_kernel(const float* __restrict__ wsv) {
    extern __shared__ float tile[];              // [128 w][129]
    const int v = blockIdx.x;
    const int tid = threadIdx.x;
    for (int idx = tid; idx < 16384; idx += 256) {
        const int u = idx >> 7, w = idx & 127;   // read coalesced in w
        tile[w * 129 + u] = wsv[(size_t)u * 16384 + (size_t)v * 128 + w];
    }
    __syncthreads();
    uint32_t* dst = (uint32_t*)(g_wt + (size_t)v * 16384);
    for (int j = tid; j < 16384; j += 256) {
        const int w = j >> 7, u = j & 127;       // write coalesced in u
        dst[w * 128 + u] = tf32r(tile[w * 129 + u]);
    }
}

// ---------------------------------------------------------------------------
// Main fused kernel: grid (128 z-tiles, 2 w-halves) = 256 CTAs,
// 128 threads (4 warps), 2 CTAs/SM. CTA tile: M=64 z, N=64 w;
// warp tile m32 x n32 (2M x 2N).
// Per v: single-pass tf32 GEMM T_v = Xs @ W[:,v,whalf] (16 k8-steps,
// 4 ldsm4 + 8 mma each), then epilogue out_i[z,w] += T_v[z,w]*xv[z,v,i].
// SMEM: A fp32 [64 rows][528B] @0 (33792B),
//       Bbuf0 [64 rows][528B] @33792, Bbuf1 @67584. Total 101376B.
// ---------------------------------------------------------------------------
#define A_STRIDE 528u
#define B_BUF0   33792u
#define B_BUF1   67584u
#define SMEM_MAIN 101376

__global__ __launch_bounds__(128, 2) void sv_mma_kernel(
    const float* __restrict__ x, float* __restrict__ out)
{
    extern __shared__ unsigned char smem[];
    const uint32_t sbase = smem_u32(smem);

    const int tid = threadIdx.x;
    const int lane = tid & 31;
    const int warp = tid >> 5;
    const int m0 = (warp >> 1) * 32;     // warp M offset (0,32)
    const int n0 = (warp & 1) * 32;      // warp N offset (0,32)
    const int z0 = blockIdx.x * 64;
    const int wbase = blockIdx.y * 64;

    // ---- A tile: 64 xs rows, tf32-rounded fp32, stride 528B ----
    {
        const int row = tid >> 1, uh = (tid & 1) * 64;
        const float4* src = (const float4*)(x + (size_t)(z0 + row) * NZ_COLS + uh);
        uint32_t* dstp = (uint32_t*)(smem + row * A_STRIDE + uh * 4u);
#pragma unroll
        for (int j = 0; j < 16; ++j) {
            float4 f = src[j];
            dstp[4 * j + 0] = tf32r(f.x);
            dstp[4 * j + 1] = tf32r(f.y);
            dstp[4 * j + 2] = tf32r(f.z);
            dstp[4 * j + 3] = tf32r(f.w);
        }
    }

    // per-lane ldmatrix offsets (row-stride 528 B)
    const uint32_t aoff = ((lane & 7) + ((lane >> 3) & 1) * 8) * A_STRIDE + ((lane >> 4) & 1) * 16u;
    const uint32_t boff = ((lane & 7) + ((lane >> 4) & 1) * 8) * A_STRIDE + ((lane >> 3) & 1) * 16u;

    // B prefetch: 32KB per v (64 w-rows x 512B), 16 x 16B per thread
#define PREFETCH_B(vv, bufaddr) do { \
    const unsigned char* gb = (const unsigned char*)g_wt + \
        (((size_t)(vv) * 128 + wbase) * 512); \
    _Pragma("unroll") \
    for (int i = 0; i < 16; ++i) { \
        int c = tid + 128 * i;              /* 0..2047 */ \
        int r = c >> 5, ch = c & 31; \
        cp16((bufaddr) + (uint32_t)r * A_STRIDE + (uint32_t)ch * 16u, \
             gb + (size_t)r * 512 + ch * 16); \
    } \
    cp_commit(); \
} while (0)

    PREFETCH_B(0, sbase + B_BUF0);

    float o[3][2][4][4];                 // out accumulators
#pragma unroll
    for (int i = 0; i < 3; ++i)
#pragma unroll
        for (int mi = 0; mi < 2; ++mi)
#pragma unroll
            for (int nf = 0; nf < 4; ++nf)
#pragma unroll
                for (int e = 0; e < 4; ++e) o[i][mi][nf][e] = 0.f;

    const int R0 = m0 + (lane >> 2);     // base z-row for this lane's frags

    const uint32_t aH0 = sbase + (uint32_t)m0 * A_STRIDE + aoff;
    const uint32_t aH1 = sbase + (uint32_t)(m0 + 16) * A_STRIDE + aoff;

    for (int v = 0; v < 128; ++v) {
        const uint32_t bufc = sbase + ((v & 1) ? B_BUF1 : B_BUF0);
        cp_wait<0>();                    // data for this v resident
        __syncthreads();                 // all warps done reading other buffer
        if (v < 127) {
            const uint32_t bufn = sbase + (((v + 1) & 1) ? B_BUF1 : B_BUF0);
            PREFETCH_B(v + 1, bufn);     // overlaps with the MMA phase below
        }

        // hoist xv loads (L1/L2)
        float xr[4][3];
#pragma unroll
        for (int j = 0; j < 4; ++j) {
            const float* p = x + (size_t)(z0 + R0 + 8 * j) * NZ_COLS + MULV + 3 * v;
            xr[j][0] = __ldg(p); xr[j][1] = __ldg(p + 1); xr[j][2] = __ldg(p + 2);
        }

        float c[2][4][4];
#pragma unroll
        for (int mi = 0; mi < 2; ++mi)
#pragma unroll
            for (int nf = 0; nf < 4; ++nf)
#pragma unroll
                for (int e = 0; e < 4; ++e) c[mi][nf][e] = 0.f;

        const uint32_t bN0 = bufc + (uint32_t)n0 * A_STRIDE + boff;
        const uint32_t bN1 = bufc + (uint32_t)(n0 + 16) * A_STRIDE + boff;

        // Single-pass tf32 k-loop: 16 k8-steps, 4 ldsm4 + 8 mma each.
#pragma unroll
        for (int k0 = 0; k0 < 128; k0 += 8) {
            const uint32_t ko = (uint32_t)k0 * 4u;
            uint32_t a0[4], a1[4], b0[4], b1[4];
            ldsm4(a0, aH0 + ko);
            ldsm4(a1, aH1 + ko);
            ldsm4(b0, bN0 + ko);
            ldsm4(b1, bN1 + ko);
            mma_tf32(c[0][0], a0, b0[0], b0[1]);
            mma_tf32(c[0][1], a0, b0[2], b0[3]);
            mma_tf32(c[0][2], a0, b1[0], b1[1]);
            mma_tf32(c[0][3], a0, b1[2], b1[3]);
            mma_tf32(c[1][0], a1, b0[0], b0[1]);
            mma_tf32(c[1][1], a1, b0[2], b0[3]);
            mma_tf32(c[1][2], a1, b1[0], b1[1]);
            mma_tf32(c[1][3], a1, b1[2], b1[3]);
        }

        // epilogue: out_i += T * xv
#pragma unroll
        for (int mi = 0; mi < 2; ++mi)
#pragma unroll
            for (int e = 0; e < 4; ++e) {
                const int rj = 2 * mi + (e >> 1);
#pragma unroll
                for (int nf = 0; nf < 4; ++nf) {
                    const float t = c[mi][nf][e];
                    o[0][mi][nf][e] += t * xr[rj][0];
                    o[1][mi][nf][e] += t * xr[rj][1];
                    o[2][mi][nf][e] += t * xr[rj][2];
                }
            }
    }

    // final store: out[z][128 + 3w + i] = PW_SV * o
#pragma unroll
    for (int mi = 0; mi < 2; ++mi)
#pragma unroll
        for (int e = 0; e < 4; ++e) {
            const int row = z0 + R0 + 16 * mi + 8 * (e >> 1);
#pragma unroll
            for (int nf = 0; nf < 4; ++nf) {
                const int w = wbase + n0 + 8 * nf + (lane & 3) * 2 + (e & 1);
                float* p = out + (size_t)row * NZ_COLS + MULV + 3 * w;
                p[0] = PW_SV * o[0][mi][nf][e];
                p[1] = PW_SV * o[1][mi][nf][e];
                p[2] = PW_SV * o[2][mi][nf][e];
            }
        }
}

// ---------------------------------------------------------------------------
// Scalar kernel (unchanged)
// ---------------------------------------------------------------------------
__global__ __launch_bounds__(512) void scalar_kernel(
    const float* __restrict__ x, const float* __restrict__ w_ss,
    const float* __restrict__ w_vv, float* __restrict__ out)
{
    extern __shared__ float smemf[];
    float* xt   = smemf;
    float* wsst = smemf + K2_ZT * NZ_COLS;
    float* wvvt = wsst + 128 * 132;

    const int tid = threadIdx.x;
    const int z0  = blockIdx.x * K2_ZT;

    for (int i = tid; i < K2_ZT * NZ_COLS / 4; i += 512)
        ((float4*)xt)[i] = ((const float4*)(x + (size_t)z0 * NZ_COLS))[i];
    for (int i = tid; i < 16384; i += 512) {
        int r = i >> 7, c = i & 127;
        wsst[c * 132 + r] = w_ss[i];
        wvvt[c * 132 + r] = w_vv[i];
    }
    __syncthreads();

    const int tx = tid & 31, ty = tid >> 5;
    const int u = tx * 4, zl = ty * 2;

    float ass[2][4], av0[2][4], av1[2][4], av2[2][4];
#pragma unroll
    for (int j = 0; j < 2; ++j)
#pragma unroll
        for (int k = 0; k < 4; ++k) { ass[j][k]=0.f; av0[j][k]=0.f; av1[j][k]=0.f; av2[j][k]=0.f; }

#pragma unroll 4
    for (int v = 0; v < 128; ++v) {
        float4 ws4 = *(const float4*)(wsst + v * 132 + u);
        float4 wv4 = *(const float4*)(wvvt + v * 132 + u);
        float wsa[4] = {ws4.x, ws4.y, ws4.z, ws4.w};
        float wva[4] = {wv4.x, wv4.y, wv4.z, wv4.w};
#pragma unroll
        for (int jz = 0; jz < 2; ++jz) {
            const float* row = xt + (zl + jz) * NZ_COLS;
            float xsv = row[v];
            float a0 = row[MULV + v*3], a1 = row[MULV + v*3 + 1], a2 = row[MULV + v*3 + 2];
#pragma unroll
            for (int k = 0; k < 4; ++k) {
                ass[jz][k] += wsa[k] * xsv;
                av0[jz][k] += wva[k] * a0;
                av1[jz][k] += wva[k] * a1;
                av2[jz][k] += wva[k] * a2;
            }
        }
    }
#pragma unroll
    for (int jz = 0; jz < 2; ++jz) {
        const int z = z0 + zl + jz;
        const float* row = xt + (zl + jz) * NZ_COLS;
        float res[4];
#pragma unroll
        for (int k = 0; k < 4; ++k) {
            int uu = u + k;
            float xsu = row[uu];
            float b0 = row[MULV + uu*3], b1 = row[MULV + uu*3 + 1], b2 = row[MULV + uu*3 + 2];
            res[k] = PW_SS * xsu * ass[jz][k] +
                     PW_VV * (b0 * av0[jz][k] + b1 * av1[jz][k] + b2 * av2[jz][k]);
        }
        float4 r4 = {res[0], res[1], res[2], res[3]};
        *(float4*)(out + (size_t)z * NZ_COLS + u) = r4;
    }
}

// ---------------------------------------------------------------------------
extern "C" void kernel_launch(void* const* d_in, const int* in_sizes, int n_in,
                              void* d_out, int out_size)
{
    const float* x    = (const float*)d_in[0];
    const float* w_ss = (const float*)d_in[1];
    const float* w_sv = (const float*)d_in[2];
    const float* w_vv = (const float*)d_in[3];
    float* out = (float*)d_out;

    const int n = in_sizes[0] / NZ_COLS;           // 8192
    const int pack_smem = 128 * 129 * 4;           // ~66 KB
    const int k2_smem   = (K2_ZT * NZ_COLS + 2 * 128 * 132) * 4;

    cudaFuncSetAttribute(pack_b_kernel, cudaFuncAttributeMaxDynamicSharedMemorySize, pack_smem);
    cudaFuncSetAttribute(sv_mma_kernel, cudaFuncAttributeMaxDynamicSharedMemorySize, SMEM_MAIN);
    cudaFuncSetAttribute(scalar_kernel, cudaFuncAttributeMaxDynamicSharedMemorySize, k2_smem);

    pack_b_kernel<<<128, 256, pack_smem>>>(w_sv);
    scalar_kernel<<<n / K2_ZT, 512, k2_smem>>>(x, w_ss, w_vv, out);
    sv_mma_kernel<<<dim3(n / 64, 2), 128, SMEM_MAIN>>>(x, out);
}

// round 11
// speedup vs baseline: 1.5454x; 1.5454x over previous
#include <cuda_runtime.h>
#include <cuda_fp16.h>
#include <cstdint>

#define MULV    128
#define NZ_COLS 512
#define PW_SS 0.0625f
#define PW_VV 0.03608439182435161f
#define PW_SV 0.0078125f
#define K2_ZT 32

// Packed weights: g_wp[v][w][u] fp16 (4.2 MB), row = 128 u * 2B = 256B
__device__ unsigned char g_wp[128u * 128u * 256u];

// ---------------- helpers ----------------
__device__ __forceinline__ uint32_t smem_u32(const void* p) {
    uint32_t a;
    asm("{ .reg .u64 t; cvta.to.shared.u64 t, %1; cvt.u32.u64 %0, t; }" : "=r"(a) : "l"(p));
    return a;
}
__device__ __forceinline__ void ldsm4(uint32_t r[4], uint32_t addr) {
    asm volatile("ldmatrix.sync.aligned.m8n8.x4.shared.b16 {%0,%1,%2,%3}, [%4];"
                 : "=r"(r[0]), "=r"(r[1]), "=r"(r[2]), "=r"(r[3]) : "r"(addr));
}
__device__ __forceinline__ void mma_f16(float c[4], const uint32_t a[4],
                                        uint32_t b0, uint32_t b1) {
    asm volatile("mma.sync.aligned.m16n8k16.row.col.f32.f16.f16.f32 "
                 "{%0,%1,%2,%3}, {%4,%5,%6,%7}, {%8,%9}, {%0,%1,%2,%3};"
                 : "+f"(c[0]), "+f"(c[1]), "+f"(c[2]), "+f"(c[3])
                 : "r"(a[0]), "r"(a[1]), "r"(a[2]), "r"(a[3]), "r"(b0), "r"(b1));
}
__device__ __forceinline__ void cp16(uint32_t sdst, const void* gsrc) {
    asm volatile("cp.async.cg.shared.global [%0], [%1], 16;" :: "r"(sdst), "l"(gsrc));
}
__device__ __forceinline__ void cp_commit() { asm volatile("cp.async.commit_group;"); }
template <int N> __device__ __forceinline__ void cp_wait() {
    asm volatile("cp.async.wait_group %0;" :: "n"(N));
}
__device__ __forceinline__ uint32_t pack_h2(float f0, float f1) {
    __half h0 = __float2half_rn(f0), h1 = __float2half_rn(f1);
    return (uint32_t)__half_as_ushort(h0) | ((uint32_t)__half_as_ushort(h1) << 16);
}

// ---------------------------------------------------------------------------
// Pack w_sv[u][v][w] -> g_wp[v][w][u] fp16. One block per v.
// ---------------------------------------------------------------------------
__global__ void pack_b_kernel(const float* __restrict__ wsv) {
    extern __shared__ float tile[];              // [128 w][133]
    const int v = blockIdx.x;
    const int tid = threadIdx.x;
    for (int idx = tid; idx < 16384; idx += 256) {
        const int u = idx >> 7, w = idx & 127;   // coalesced in w
        tile[w * 133 + u] = wsv[(size_t)u * 16384 + (size_t)v * 128 + w];
    }
    __syncthreads();
    for (int j = tid; j < 8192; j += 256) {
        const int w = j >> 6, u0 = (j & 63) * 2;
        uint32_t* dst = (uint32_t*)(g_wp + ((size_t)v * 128 + w) * 256);
        dst[u0 >> 1] = pack_h2(tile[w * 133 + u0], tile[w * 133 + u0 + 1]);
    }
}

// ---------------------------------------------------------------------------
// Main fused kernel: grid (64 z-tiles, 2 w-halves) = 128 CTAs, 256 threads
// (8 warps). CTA tile M=128 z, N=64 w; warp tile m32 x n32 (4M x 2N).
// Per v: single-pass fp16 GEMM T_v = Xs @ W[:,v,whalf]
// (8 k16-steps, 4 ldsm4 + 8 mma each), then out_i[z,w] += T_v[z,w]*xv[z,v,i].
// SMEM (bytes): A fp16 [128 rows][272B] @0 (34816),
//   Bbuf0 [64 rows][272B] @34816 (17408), Bbuf1 @52224. Total 69632.
// ---------------------------------------------------------------------------
#define B_BUF0 34816u
#define B_BUF1 52224u
#define SMEM_MAIN 69632

__global__ __launch_bounds__(256, 1) void sv_mma_kernel(
    const float* __restrict__ x, float* __restrict__ out)
{
    extern __shared__ unsigned char smem[];
    const uint32_t sbase = smem_u32(smem);

    const int tid = threadIdx.x;
    const int lane = tid & 31;
    const int warp = tid >> 5;
    const int m0 = (warp >> 1) * 32;     // warp M offset (0,32,64,96)
    const int n0 = (warp & 1) * 32;      // warp N offset (0,32)
    const int z0 = blockIdx.x * 128;
    const int wbase = blockIdx.y * 64;

    // ---- A tile: convert xs rows to fp16 in smem (stride 272B) ----
    {
        const int row = tid >> 1, uh = (tid & 1) * 64;
        const float4* src = (const float4*)(x + (size_t)(z0 + row) * NZ_COLS + uh);
        uint32_t* dst = (uint32_t*)(smem + row * 272u + uh * 2u);
#pragma unroll
        for (int j = 0; j < 16; ++j) {
            float4 f = src[j];
            dst[2 * j]     = pack_h2(f.x, f.y);
            dst[2 * j + 1] = pack_h2(f.z, f.w);
        }
    }

    // per-lane ldmatrix offsets (row-stride 272 B) — proven in R6 (b16 path)
    const uint32_t aoff = ((lane & 7) + ((lane >> 3) & 1) * 8) * 272u + ((lane >> 4) & 1) * 16u;
    const uint32_t boff = ((lane & 7) + ((lane >> 4) & 1) * 8) * 272u + ((lane >> 3) & 1) * 16u;

    // B prefetch: 16KB per v (64 w-rows x 256B), 4 x 16B per thread
#define PREFETCH_B(vv, bufaddr) do { \
    const unsigned char* gb = g_wp + ((size_t)(vv) * 128 + wbase) * 256; \
    _Pragma("unroll") \
    for (int i = 0; i < 4; ++i) { \
        int c = tid + 256 * i;              /* 0..1023 */ \
        int r = c >> 4, ch = c & 15; \
        cp16((bufaddr) + (uint32_t)r * 272u + (uint32_t)ch * 16u, \
             gb + (size_t)r * 256 + ch * 16); \
    } \
    cp_commit(); \
} while (0)

    PREFETCH_B(0, sbase + B_BUF0);

    float o[3][2][4][4];                 // out accumulators
#pragma unroll
    for (int i = 0; i < 3; ++i)
#pragma unroll
        for (int mi = 0; mi < 2; ++mi)
#pragma unroll
            for (int nf = 0; nf < 4; ++nf)
#pragma unroll
                for (int e = 0; e < 4; ++e) o[i][mi][nf][e] = 0.f;

    const int R0 = m0 + (lane >> 2);     // base z-row for this lane's frags

    const uint32_t aH0 = sbase + (uint32_t)m0 * 272u + aoff;
    const uint32_t aH1 = sbase + (uint32_t)(m0 + 16) * 272u + aoff;

    for (int v = 0; v < 128; ++v) {
        const uint32_t bufc = sbase + ((v & 1) ? B_BUF1 : B_BUF0);
        cp_wait<0>();                    // data for this v resident
        __syncthreads();                 // all warps done reading other buffer
        if (v < 127) {
            const uint32_t bufn = sbase + (((v + 1) & 1) ? B_BUF1 : B_BUF0);
            PREFETCH_B(v + 1, bufn);     // overlaps with MMA phase below
        }

        // hoist xv loads (L1/L2)
        float xr[4][3];
#pragma unroll
        for (int j = 0; j < 4; ++j) {
            const float* p = x + (size_t)(z0 + R0 + 8 * j) * NZ_COLS + MULV + 3 * v;
            xr[j][0] = __ldg(p); xr[j][1] = __ldg(p + 1); xr[j][2] = __ldg(p + 2);
        }

        float c[2][4][4];
#pragma unroll
        for (int mi = 0; mi < 2; ++mi)
#pragma unroll
            for (int nf = 0; nf < 4; ++nf)
#pragma unroll
                for (int e = 0; e < 4; ++e) c[mi][nf][e] = 0.f;

        const uint32_t bN0 = bufc + (uint32_t)n0 * 272u + boff;
        const uint32_t bN1 = bufc + (uint32_t)(n0 + 16) * 272u + boff;

        // Single-pass fp16 k-loop: 8 k16-steps, 4 ldsm4 + 8 mma each.
#pragma unroll
        for (int k0 = 0; k0 < 128; k0 += 16) {
            const uint32_t ko = (uint32_t)k0 * 2u;
            uint32_t a0[4], a1[4], b0[4], b1[4];
            ldsm4(a0, aH0 + ko);
            ldsm4(a1, aH1 + ko);
            ldsm4(b0, bN0 + ko);
            ldsm4(b1, bN1 + ko);
            mma_f16(c[0][0], a0, b0[0], b0[1]);
            mma_f16(c[0][1], a0, b0[2], b0[3]);
            mma_f16(c[0][2], a0, b1[0], b1[1]);
            mma_f16(c[0][3], a0, b1[2], b1[3]);
            mma_f16(c[1][0], a1, b0[0], b0[1]);
            mma_f16(c[1][1], a1, b0[2], b0[3]);
            mma_f16(c[1][2], a1, b1[0], b1[1]);
            mma_f16(c[1][3], a1, b1[2], b1[3]);
        }

        // epilogue: out_i += T * xv
#pragma unroll
        for (int mi = 0; mi < 2; ++mi)
#pragma unroll
            for (int e = 0; e < 4; ++e) {
                const int rj = 2 * mi + (e >> 1);
#pragma unroll
                for (int nf = 0; nf < 4; ++nf) {
                    const float t = c[mi][nf][e];
                    o[0][mi][nf][e] += t * xr[rj][0];
                    o[1][mi][nf][e] += t * xr[rj][1];
                    o[2][mi][nf][e] += t * xr[rj][2];
                }
            }
    }

    // final store: out[z][128 + 3w + i] = PW_SV * o
#pragma unroll
    for (int mi = 0; mi < 2; ++mi)
#pragma unroll
        for (int e = 0; e < 4; ++e) {
            const int row = z0 + R0 + 16 * mi + 8 * (e >> 1);
#pragma unroll
            for (int nf = 0; nf < 4; ++nf) {
                const int w = wbase + n0 + 8 * nf + (lane & 3) * 2 + (e & 1);
                float* p = out + (size_t)row * NZ_COLS + MULV + 3 * w;
                p[0] = PW_SV * o[0][mi][nf][e];
                p[1] = PW_SV * o[1][mi][nf][e];
                p[2] = PW_SV * o[2][mi][nf][e];
            }
        }
}

// ---------------------------------------------------------------------------
// Scalar kernel (unchanged)
// ---------------------------------------------------------------------------
__global__ __launch_bounds__(512) void scalar_kernel(
    const float* __restrict__ x, const float* __restrict__ w_ss,
    const float* __restrict__ w_vv, float* __restrict__ out)
{
    extern __shared__ float smemf[];
    float* xt   = smemf;
    float* wsst = smemf + K2_ZT * NZ_COLS;
    float* wvvt = wsst + 128 * 132;

    const int tid = threadIdx.x;
    const int z0  = blockIdx.x * K2_ZT;

    for (int i = tid; i < K2_ZT * NZ_COLS / 4; i += 512)
        ((float4*)xt)[i] = ((const float4*)(x + (size_t)z0 * NZ_COLS))[i];
    for (int i = tid; i < 16384; i += 512) {
        int r = i >> 7, c = i & 127;
        wsst[c * 132 + r] = w_ss[i];
        wvvt[c * 132 + r] = w_vv[i];
    }
    __syncthreads();

    const int tx = tid & 31, ty = tid >> 5;
    const int u = tx * 4, zl = ty * 2;

    float ass[2][4], av0[2][4], av1[2][4], av2[2][4];
#pragma unroll
    for (int j = 0; j < 2; ++j)
#pragma unroll
        for (int k = 0; k < 4; ++k) { ass[j][k]=0.f; av0[j][k]=0.f; av1[j][k]=0.f; av2[j][k]=0.f; }

#pragma unroll 4
    for (int v = 0; v < 128; ++v) {
        float4 ws4 = *(const float4*)(wsst + v * 132 + u);
        float4 wv4 = *(const float4*)(wvvt + v * 132 + u);
        float wsa[4] = {ws4.x, ws4.y, ws4.z, ws4.w};
        float wva[4] = {wv4.x, wv4.y, wv4.z, wv4.w};
#pragma unroll
        for (int jz = 0; jz < 2; ++jz) {
            const float* row = xt + (zl + jz) * NZ_COLS;
            float xsv = row[v];
            float a0 = row[MULV + v*3], a1 = row[MULV + v*3 + 1], a2 = row[MULV + v*3 + 2];
#pragma unroll
            for (int k = 0; k < 4; ++k) {
                ass[jz][k] += wsa[k] * xsv;
                av0[jz][k] += wva[k] * a0;
                av1[jz][k] += wva[k] * a1;
                av2[jz][k] += wva[k] * a2;
            }
        }
    }
#pragma unroll
    for (int jz = 0; jz < 2; ++jz) {
        const int z = z0 + zl + jz;
        const float* row = xt + (zl + jz) * NZ_COLS;
        float res[4];
#pragma unroll
        for (int k = 0; k < 4; ++k) {
            int uu = u + k;
            float xsu = row[uu];
            float b0 = row[MULV + uu*3], b1 = row[MULV + uu*3 + 1], b2 = row[MULV + uu*3 + 2];
            res[k] = PW_SS * xsu * ass[jz][k] +
                     PW_VV * (b0 * av0[jz][k] + b1 * av1[jz][k] + b2 * av2[jz][k]);
        }
        float4 r4 = {res[0], res[1], res[2], res[3]};
        *(float4*)(out + (size_t)z * NZ_COLS + u) = r4;
    }
}

// ---------------------------------------------------------------------------
extern "C" void kernel_launch(void* const* d_in, const int* in_sizes, int n_in,
                              void* d_out, int out_size)
{
    const float* x    = (const float*)d_in[0];
    const float* w_ss = (const float*)d_in[1];
    const float* w_sv = (const float*)d_in[2];
    const float* w_vv = (const float*)d_in[3];
    float* out = (float*)d_out;

    const int n = in_sizes[0] / NZ_COLS;           // 8192
    const int pack_smem = 128 * 133 * 4;           // ~68 KB
    const int k2_smem   = (K2_ZT * NZ_COLS + 2 * 128 * 132) * 4;

    cudaFuncSetAttribute(pack_b_kernel, cudaFuncAttributeMaxDynamicSharedMemorySize, pack_smem);
    cudaFuncSetAttribute(sv_mma_kernel, cudaFuncAttributeMaxDynamicSharedMemorySize, SMEM_MAIN);
    cudaFuncSetAttribute(scalar_kernel, cudaFuncAttributeMaxDynamicSharedMemorySize, k2_smem);

    pack_b_kernel<<<128, 256, pack_smem>>>(w_sv);
    scalar_kernel<<<n / K2_ZT, 512, k2_smem>>>(x, w_ss, w_vv, out);
    sv_mma_kernel<<<dim3(n / 128, 2), 256, SMEM_MAIN>>>(x, out);
}

// round 12
// speedup vs baseline: 1.6002x; 1.0354x over previous
#include <cuda_runtime.h>
#include <cuda_fp16.h>
#include <cstdint>

#define MULV    128
#define NZ_COLS 512
#define PW_SS 0.0625f
#define PW_VV 0.03608439182435161f
#define PW_SV 0.0078125f

// Packed weights (fp16): g_wp[v][w][u] (4.2 MB), g_wss[u][v], g_wvv[u][v] (32 KB each)
__device__ unsigned char g_wp[128u * 128u * 256u];
__device__ unsigned char g_wss[128u * 256u];
__device__ unsigned char g_wvv[128u * 256u];

// ---------------- helpers ----------------
__device__ __forceinline__ uint32_t smem_u32(const void* p) {
    uint32_t a;
    asm("{ .reg .u64 t; cvta.to.shared.u64 t, %1; cvt.u32.u64 %0, t; }" : "=r"(a) : "l"(p));
    return a;
}
__device__ __forceinline__ void ldsm4(uint32_t r[4], uint32_t addr) {
    asm volatile("ldmatrix.sync.aligned.m8n8.x4.shared.b16 {%0,%1,%2,%3}, [%4];"
                 : "=r"(r[0]), "=r"(r[1]), "=r"(r[2]), "=r"(r[3]) : "r"(addr));
}
__device__ __forceinline__ void mma_f16(float c[4], const uint32_t a[4],
                                        uint32_t b0, uint32_t b1) {
    asm volatile("mma.sync.aligned.m16n8k16.row.col.f32.f16.f16.f32 "
                 "{%0,%1,%2,%3}, {%4,%5,%6,%7}, {%8,%9}, {%0,%1,%2,%3};"
                 : "+f"(c[0]), "+f"(c[1]), "+f"(c[2]), "+f"(c[3])
                 : "r"(a[0]), "r"(a[1]), "r"(a[2]), "r"(a[3]), "r"(b0), "r"(b1));
}
__device__ __forceinline__ void cp16(uint32_t sdst, const void* gsrc) {
    asm volatile("cp.async.cg.shared.global [%0], [%1], 16;" :: "r"(sdst), "l"(gsrc));
}
__device__ __forceinline__ void cp_commit() { asm volatile("cp.async.commit_group;"); }
template <int N> __device__ __forceinline__ void cp_wait() {
    asm volatile("cp.async.wait_group %0;" :: "n"(N));
}
__device__ __forceinline__ uint32_t pack_h2(float f0, float f1) {
    __half h0 = __float2half_rn(f0), h1 = __float2half_rn(f1);
    return (uint32_t)__half_as_ushort(h0) | ((uint32_t)__half_as_ushort(h1) << 16);
}

// ---------------------------------------------------------------------------
// Pack: blocks 0-127: w_sv[u][v][w] -> g_wp[v][w][u] fp16.
//       block 128: w_ss -> g_wss fp16 ([u][v], direct). block 129: w_vv.
// ---------------------------------------------------------------------------
__global__ void pack_b_kernel(const float* __restrict__ wsv,
                              const float* __restrict__ wss,
                              const float* __restrict__ wvv) {
    extern __shared__ float tile[];              // [128 w][133]
    const int tid = threadIdx.x;
    if (blockIdx.x >= 128) {
        const float* src = (blockIdx.x == 128) ? wss : wvv;
        uint32_t* dst = (uint32_t*)((blockIdx.x == 128) ? g_wss : g_wvv);
        for (int j = tid; j < 8192; j += 256)
            dst[j] = pack_h2(src[2 * j], src[2 * j + 1]);
        return;
    }
    const int v = blockIdx.x;
    for (int idx = tid; idx < 16384; idx += 256) {
        const int u = idx >> 7, w = idx & 127;   // coalesced in w
        tile[w * 133 + u] = wsv[(size_t)u * 16384 + (size_t)v * 128 + w];
    }
    __syncthreads();
    for (int j = tid; j < 8192; j += 256) {
        const int w = j >> 6, u0 = (j & 63) * 2;
        uint32_t* dst = (uint32_t*)(g_wp + ((size_t)v * 128 + w) * 256);
        dst[u0 >> 1] = pack_h2(tile[w * 133 + u0], tile[w * 133 + u0 + 1]);
    }
}

// ---------------------------------------------------------------------------
// Fully fused kernel: grid (64 z-tiles, 2 halves) = 128 CTAs, 256 threads.
// CTA tile M=128 z, N=64 (w-half, and the same 64-column u-half of out_s).
// it 0..127: v-iterations (as R11). it=128: ss GEMM (A=xs, B=w_ss half).
// it=129: three vv GEMMs (A=xv_i tiles, shared B=w_vv half).
// SMEM: A_xs @0, A_xv0 @34816, A_xv1 @69632, A_xv2 @104448 (each 128x272B),
//       Bbuf0 @139264, Bbuf1 @156672 (each 64x272B). Total 174080.
// ---------------------------------------------------------------------------
#define A_XV(i)  (34816u * (1u + (i)))
#define B_BUF0   139264u
#define SMEM_MAIN 174080

__global__ __launch_bounds__(256, 1) void sv_mma_kernel(
    const float* __restrict__ x, float* __restrict__ out)
{
    extern __shared__ unsigned char smem[];
    const uint32_t sbase = smem_u32(smem);

    const int tid = threadIdx.x;
    const int lane = tid & 31;
    const int warp = tid >> 5;
    const int m0 = (warp >> 1) * 32;
    const int n0 = (warp & 1) * 32;
    const int z0 = blockIdx.x * 128;
    const int wbase = blockIdx.y * 64;   // w-half AND u-half

    // ---- A_xs tile: fp16, stride 272B ----
    {
        const int row = tid >> 1, uh = (tid & 1) * 64;
        const float4* src = (const float4*)(x + (size_t)(z0 + row) * NZ_COLS + uh);
        uint32_t* dst = (uint32_t*)(smem + row * 272u + uh * 2u);
#pragma unroll
        for (int j = 0; j < 16; ++j) {
            float4 f = src[j];
            dst[2 * j]     = pack_h2(f.x, f.y);
            dst[2 * j + 1] = pack_h2(f.z, f.w);
        }
    }
    // ---- A_xv tiles: de-interleave xv components into 3 fp16 tiles ----
    {
        const int row = tid >> 1;
        const int c0 = (tid & 1) * 192;
        const float4* src = (const float4*)(x + (size_t)(z0 + row) * NZ_COLS + MULV + c0);
#pragma unroll 8
        for (int j = 0; j < 48; ++j) {
            float4 f = src[j];
            float vals[4] = {f.x, f.y, f.z, f.w};
#pragma unroll
            for (int t = 0; t < 4; ++t) {
                int cc = c0 + 4 * j + t;
                int v = cc / 3, i = cc - 3 * v;
                *(__half*)(smem + A_XV(i) + row * 272u + v * 2u) = __float2half_rn(vals[t]);
            }
        }
    }

    const uint32_t aoff = ((lane & 7) + ((lane >> 3) & 1) * 8) * 272u + ((lane >> 4) & 1) * 16u;
    const uint32_t boff = ((lane & 7) + ((lane >> 4) & 1) * 8) * 272u + ((lane >> 3) & 1) * 16u;

#define BSRC(it) ((it) < 128 ? (const unsigned char*)g_wp + ((size_t)(it) * 128 + wbase) * 256 \
                 : (it) == 128 ? g_wss + (size_t)wbase * 256 : g_wvv + (size_t)wbase * 256)

#define PREFETCH_B(gsrc, bufaddr) do { \
    const unsigned char* _g = (gsrc); \
    _Pragma("unroll") \
    for (int i = 0; i < 4; ++i) { \
        int c = tid + 256 * i; \
        int r = c >> 4, ch = c & 15; \
        cp16((bufaddr) + (uint32_t)r * 272u + (uint32_t)ch * 16u, \
             _g + (size_t)r * 256 + ch * 16); \
    } \
    cp_commit(); \
} while (0)

#define GEMM_F16(cc, aB0, aB1, bN0, bN1) do { \
    _Pragma("unroll") \
    for (int k0 = 0; k0 < 128; k0 += 16) { \
        const uint32_t ko = (uint32_t)k0 * 2u; \
        uint32_t a0[4], a1[4], b0[4], b1[4]; \
        ldsm4(a0, (aB0) + ko); \
        ldsm4(a1, (aB1) + ko); \
        ldsm4(b0, (bN0) + ko); \
        ldsm4(b1, (bN1) + ko); \
        mma_f16((cc)[0][0], a0, b0[0], b0[1]); \
        mma_f16((cc)[0][1], a0, b0[2], b0[3]); \
        mma_f16((cc)[0][2], a0, b1[0], b1[1]); \
        mma_f16((cc)[0][3], a0, b1[2], b1[3]); \
        mma_f16((cc)[1][0], a1, b0[0], b0[1]); \
        mma_f16((cc)[1][1], a1, b0[2], b0[3]); \
        mma_f16((cc)[1][2], a1, b1[0], b1[1]); \
        mma_f16((cc)[1][3], a1, b1[2], b1[3]); \
    } \
} while (0)

    PREFETCH_B(BSRC(0), sbase + B_BUF0);

    float o[3][2][4][4];                 // out_v accumulators
    float o2[2][4][4];                   // out_s accumulators
#pragma unroll
    for (int mi = 0; mi < 2; ++mi)
#pragma unroll
        for (int nf = 0; nf < 4; ++nf)
#pragma unroll
            for (int e = 0; e < 4; ++e) {
                o[0][mi][nf][e] = 0.f; o[1][mi][nf][e] = 0.f; o[2][mi][nf][e] = 0.f;
                o2[mi][nf][e] = 0.f;
            }

    const int R0 = m0 + (lane >> 2);
    const uint32_t aH0 = sbase + (uint32_t)m0 * 272u + aoff;
    const uint32_t aH1 = sbase + (uint32_t)(m0 + 16) * 272u + aoff;

    for (int it = 0; it <= 129; ++it) {
        const uint32_t bufc = sbase + B_BUF0 + (uint32_t)(it & 1) * 17408u;
        cp_wait<0>();
        __syncthreads();
        if (it < 129) {
            const uint32_t bufn = sbase + B_BUF0 + (uint32_t)((it + 1) & 1) * 17408u;
            PREFETCH_B(BSRC(it + 1), bufn);
        }

        const uint32_t bN0 = bufc + (uint32_t)n0 * 272u + boff;
        const uint32_t bN1 = bufc + (uint32_t)(n0 + 16) * 272u + boff;

        if (it < 128) {
            // ---- vector term: v = it ----
            float xr[4][3];
#pragma unroll
            for (int j = 0; j < 4; ++j) {
                const float* p = x + (size_t)(z0 + R0 + 8 * j) * NZ_COLS + MULV + 3 * it;
                xr[j][0] = __ldg(p); xr[j][1] = __ldg(p + 1); xr[j][2] = __ldg(p + 2);
            }
            float c[2][4][4];
#pragma unroll
            for (int mi = 0; mi < 2; ++mi)
#pragma unroll
                for (int nf = 0; nf < 4; ++nf)
#pragma unroll
                    for (int e = 0; e < 4; ++e) c[mi][nf][e] = 0.f;
            GEMM_F16(c, aH0, aH1, bN0, bN1);
#pragma unroll
            for (int mi = 0; mi < 2; ++mi)
#pragma unroll
                for (int e = 0; e < 4; ++e) {
                    const int rj = 2 * mi + (e >> 1);
#pragma unroll
                    for (int nf = 0; nf < 4; ++nf) {
                        const float t = c[mi][nf][e];
                        o[0][mi][nf][e] += t * xr[rj][0];
                        o[1][mi][nf][e] += t * xr[rj][1];
                        o[2][mi][nf][e] += t * xr[rj][2];
                    }
                }
        } else if (it == 128) {
            // ---- ss term: T[z,u] = sum_v w_ss[u,v] xs[z,v] ----
            float c[2][4][4];
#pragma unroll
            for (int mi = 0; mi < 2; ++mi)
#pragma unroll
                for (int nf = 0; nf < 4; ++nf)
#pragma unroll
                    for (int e = 0; e < 4; ++e) c[mi][nf][e] = 0.f;
            GEMM_F16(c, aH0, aH1, bN0, bN1);
#pragma unroll
            for (int mi = 0; mi < 2; ++mi)
#pragma unroll
                for (int e = 0; e < 4; ++e) {
                    const int row = z0 + R0 + 16 * mi + 8 * (e >> 1);
#pragma unroll
                    for (int nf = 0; nf < 4; ++nf) {
                        const int u = wbase + n0 + 8 * nf + (lane & 3) * 2 + (e & 1);
                        o2[mi][nf][e] += PW_SS * __ldg(x + (size_t)row * NZ_COLS + u) * c[mi][nf][e];
                    }
                }
        } else {
            // ---- vv terms: 3 GEMMs sharing B = w_vv half ----
#pragma unroll 1
            for (int i = 0; i < 3; ++i) {
                const uint32_t aV0 = sbase + A_XV(i) + (uint32_t)m0 * 272u + aoff;
                const uint32_t aV1 = sbase + A_XV(i) + (uint32_t)(m0 + 16) * 272u + aoff;
                float c[2][4][4];
#pragma unroll
                for (int mi = 0; mi < 2; ++mi)
#pragma unroll
                    for (int nf = 0; nf < 4; ++nf)
#pragma unroll
                        for (int e = 0; e < 4; ++e) c[mi][nf][e] = 0.f;
                GEMM_F16(c, aV0, aV1, bN0, bN1);
#pragma unroll
                for (int mi = 0; mi < 2; ++mi)
#pragma unroll
                    for (int e = 0; e < 4; ++e) {
                        const int row = z0 + R0 + 16 * mi + 8 * (e >> 1);
#pragma unroll
                        for (int nf = 0; nf < 4; ++nf) {
                            const int u = wbase + n0 + 8 * nf + (lane & 3) * 2 + (e & 1);
                            o2[mi][nf][e] += PW_VV *
                                __ldg(x + (size_t)row * NZ_COLS + MULV + 3 * u + i) * c[mi][nf][e];
                        }
                    }
            }
        }
    }

    // final stores
#pragma unroll
    for (int mi = 0; mi < 2; ++mi)
#pragma unroll
        for (int e = 0; e < 4; ++e) {
            const int row = z0 + R0 + 16 * mi + 8 * (e >> 1);
#pragma unroll
            for (int nf = 0; nf < 4; ++nf) {
                const int w = wbase + n0 + 8 * nf + (lane & 3) * 2 + (e & 1);
                float* p = out + (size_t)row * NZ_COLS + MULV + 3 * w;
                p[0] = PW_SV * o[0][mi][nf][e];
                p[1] = PW_SV * o[1][mi][nf][e];
                p[2] = PW_SV * o[2][mi][nf][e];
                out[(size_t)row * NZ_COLS + w] = o2[mi][nf][e];
            }
        }
}

// ---------------------------------------------------------------------------
extern "C" void kernel_launch(void* const* d_in, const int* in_sizes, int n_in,
                              void* d_out, int out_size)
{
    const float* x    = (const float*)d_in[0];
    const float* w_ss = (const float*)d_in[1];
    const float* w_sv = (const float*)d_in[2];
    const float* w_vv = (const float*)d_in[3];
    float* out = (float*)d_out;

    const int n = in_sizes[0] / NZ_COLS;           // 8192
    const int pack_smem = 128 * 133 * 4;           // ~68 KB

    cudaFuncSetAttribute(pack_b_kernel, cudaFuncAttributeMaxDynamicSharedMemorySize, pack_smem);
    cudaFuncSetAttribute(sv_mma_kernel, cudaFuncAttributeMaxDynamicSharedMemorySize, SMEM_MAIN);

    pack_b_kernel<<<130, 256, pack_smem>>>(w_sv, w_ss, w_vv);
    sv_mma_kernel<<<dim3(n / 128, 2), 256, SMEM_MAIN>>>(x, out);
}

// round 13
// speedup vs baseline: 1.6196x; 1.0121x over previous
#include <cuda_runtime.h>
#include <cuda_fp16.h>
#include <cstdint>

#define MULV    128
#define NZ_COLS 512
#define PW_SS 0.0625f
#define PW_VV 0.03608439182435161f
#define PW_SV 0.0078125f

// Packed weights (fp16): g_wp[v][w][u] (4.2 MB), g_wss[u][v], g_wvv[u][v] (32 KB each)
__device__ unsigned char g_wp[128u * 128u * 256u];
__device__ unsigned char g_wss[128u * 256u];
__device__ unsigned char g_wvv[128u * 256u];

// ---------------- helpers ----------------
__device__ __forceinline__ uint32_t smem_u32(const void* p) {
    uint32_t a;
    asm("{ .reg .u64 t; cvta.to.shared.u64 t, %1; cvt.u32.u64 %0, t; }" : "=r"(a) : "l"(p));
    return a;
}
__device__ __forceinline__ void ldsm4(uint32_t r[4], uint32_t addr) {
    asm volatile("ldmatrix.sync.aligned.m8n8.x4.shared.b16 {%0,%1,%2,%3}, [%4];"
                 : "=r"(r[0]), "=r"(r[1]), "=r"(r[2]), "=r"(r[3]) : "r"(addr));
}
__device__ __forceinline__ void mma_f16(float c[4], const uint32_t a[4],
                                        uint32_t b0, uint32_t b1) {
    asm volatile("mma.sync.aligned.m16n8k16.row.col.f32.f16.f16.f32 "
                 "{%0,%1,%2,%3}, {%4,%5,%6,%7}, {%8,%9}, {%0,%1,%2,%3};"
                 : "+f"(c[0]), "+f"(c[1]), "+f"(c[2]), "+f"(c[3])
                 : "r"(a[0]), "r"(a[1]), "r"(a[2]), "r"(a[3]), "r"(b0), "r"(b1));
}
__device__ __forceinline__ void cp16(uint32_t sdst, const void* gsrc) {
    asm volatile("cp.async.cg.shared.global [%0], [%1], 16;" :: "r"(sdst), "l"(gsrc));
}
__device__ __forceinline__ void cp_commit() { asm volatile("cp.async.commit_group;"); }
template <int N> __device__ __forceinline__ void cp_wait() {
    asm volatile("cp.async.wait_group %0;" :: "n"(N));
}
__device__ __forceinline__ uint32_t pack_h2(float f0, float f1) {
    __half h0 = __float2half_rn(f0), h1 = __float2half_rn(f1);
    return (uint32_t)__half_as_ushort(h0) | ((uint32_t)__half_as_ushort(h1) << 16);
}

// ---------------------------------------------------------------------------
// Pack: blocks 0-127: w_sv[u][v][w] -> g_wp[v][w][u] fp16.
//       block 128: w_ss -> g_wss fp16. block 129: w_vv -> g_wvv.
// ---------------------------------------------------------------------------
__global__ void pack_b_kernel(const float* __restrict__ wsv,
                              const float* __restrict__ wss,
                              const float* __restrict__ wvv) {
    extern __shared__ float tile[];              // [128 w][133]
    const int tid = threadIdx.x;
    if (blockIdx.x >= 128) {
        const float* src = (blockIdx.x == 128) ? wss : wvv;
        uint32_t* dst = (uint32_t*)((blockIdx.x == 128) ? g_wss : g_wvv);
        for (int j = tid; j < 8192; j += 256)
            dst[j] = pack_h2(src[2 * j], src[2 * j + 1]);
        return;
    }
    const int v = blockIdx.x;
    for (int idx = tid; idx < 16384; idx += 256) {
        const int u = idx >> 7, w = idx & 127;
        tile[w * 133 + u] = wsv[(size_t)u * 16384 + (size_t)v * 128 + w];
    }
    __syncthreads();
    for (int j = tid; j < 8192; j += 256) {
        const int w = j >> 6, u0 = (j & 63) * 2;
        uint32_t* dst = (uint32_t*)(g_wp + ((size_t)v * 128 + w) * 256);
        dst[u0 >> 1] = pack_h2(tile[w * 133 + u0], tile[w * 133 + u0 + 1]);
    }
}

// ---------------------------------------------------------------------------
// Fully fused kernel: grid (64 z-tiles, 2 halves) = 128 CTAs, 256 threads.
// v-loop 0..127 (vector term, accumulators o[96]); PEELED tail: ss GEMM +
// three vv GEMMs with o2 declared locally (keeps v-loop at ~230 regs, no spill).
// SMEM: A_xs @0, A_xv0/1/2 @34816/69632/104448 (each 128x272B),
//       Bbuf0 @139264, Bbuf1 @156672 (each 64x272B). Total 174080.
// ---------------------------------------------------------------------------
#define A_XV(i)  (34816u * (1u + (i)))
#define B_BUF0   139264u
#define SMEM_MAIN 174080

__global__ __launch_bounds__(256, 1) void sv_mma_kernel(
    const float* __restrict__ x, float* __restrict__ out)
{
    extern __shared__ unsigned char smem[];
    const uint32_t sbase = smem_u32(smem);

    const int tid = threadIdx.x;
    const int lane = tid & 31;
    const int warp = tid >> 5;
    const int m0 = (warp >> 1) * 32;
    const int n0 = (warp & 1) * 32;
    const int z0 = blockIdx.x * 128;
    const int wbase = blockIdx.y * 64;   // w-half AND u-half

    // ---- A_xs tile: fp16, stride 272B ----
    {
        const int row = tid >> 1, uh = (tid & 1) * 64;
        const float4* src = (const float4*)(x + (size_t)(z0 + row) * NZ_COLS + uh);
        uint32_t* dst = (uint32_t*)(smem + row * 272u + uh * 2u);
#pragma unroll
        for (int j = 0; j < 16; ++j) {
            float4 f = src[j];
            dst[2 * j]     = pack_h2(f.x, f.y);
            dst[2 * j + 1] = pack_h2(f.z, f.w);
        }
    }
    // ---- A_xv tiles: de-interleave xv components into 3 fp16 tiles ----
    {
        const int row = tid >> 1;
        const int c0 = (tid & 1) * 192;
        const float4* src = (const float4*)(x + (size_t)(z0 + row) * NZ_COLS + MULV + c0);
#pragma unroll 8
        for (int j = 0; j < 48; ++j) {
            float4 f = src[j];
            float vals[4] = {f.x, f.y, f.z, f.w};
#pragma unroll
            for (int t = 0; t < 4; ++t) {
                int cc = c0 + 4 * j + t;
                int v = cc / 3, i = cc - 3 * v;
                *(__half*)(smem + A_XV(i) + row * 272u + v * 2u) = __float2half_rn(vals[t]);
            }
        }
    }

    const uint32_t aoff = ((lane & 7) + ((lane >> 3) & 1) * 8) * 272u + ((lane >> 4) & 1) * 16u;
    const uint32_t boff = ((lane & 7) + ((lane >> 4) & 1) * 8) * 272u + ((lane >> 3) & 1) * 16u;

#define PREFETCH_B(gsrc, bufaddr) do { \
    const unsigned char* _g = (gsrc); \
    _Pragma("unroll") \
    for (int i = 0; i < 4; ++i) { \
        int c = tid + 256 * i; \
        int r = c >> 4, ch = c & 15; \
        cp16((bufaddr) + (uint32_t)r * 272u + (uint32_t)ch * 16u, \
             _g + (size_t)r * 256 + ch * 16); \
    } \
    cp_commit(); \
} while (0)

#define GEMM_F16(cc, aB0, aB1, bN0, bN1) do { \
    _Pragma("unroll") \
    for (int k0 = 0; k0 < 128; k0 += 16) { \
        const uint32_t ko = (uint32_t)k0 * 2u; \
        uint32_t a0[4], a1[4], b0[4], b1[4]; \
        ldsm4(a0, (aB0) + ko); \
        ldsm4(a1, (aB1) + ko); \
        ldsm4(b0, (bN0) + ko); \
        ldsm4(b1, (bN1) + ko); \
        mma_f16((cc)[0][0], a0, b0[0], b0[1]); \
        mma_f16((cc)[0][1], a0, b0[2], b0[3]); \
        mma_f16((cc)[0][2], a0, b1[0], b1[1]); \
        mma_f16((cc)[0][3], a0, b1[2], b1[3]); \
        mma_f16((cc)[1][0], a1, b0[0], b0[1]); \
        mma_f16((cc)[1][1], a1, b0[2], b0[3]); \
        mma_f16((cc)[1][2], a1, b1[0], b1[1]); \
        mma_f16((cc)[1][3], a1, b1[2], b1[3]); \
    } \
} while (0)

    PREFETCH_B(g_wp + (size_t)wbase * 256, sbase + B_BUF0);

    float o[3][2][4][4];                 // out_v accumulators (persistent)
#pragma unroll
    for (int mi = 0; mi < 2; ++mi)
#pragma unroll
        for (int nf = 0; nf < 4; ++nf)
#pragma unroll
            for (int e = 0; e < 4; ++e) {
                o[0][mi][nf][e] = 0.f; o[1][mi][nf][e] = 0.f; o[2][mi][nf][e] = 0.f;
            }

    const int R0 = m0 + (lane >> 2);
    const uint32_t aH0 = sbase + (uint32_t)m0 * 272u + aoff;
    const uint32_t aH1 = sbase + (uint32_t)(m0 + 16) * 272u + aoff;

    // =================== v-loop (vector term only) ===================
    for (int it = 0; it < 128; ++it) {
        const uint32_t bufc = sbase + B_BUF0 + (uint32_t)(it & 1) * 17408u;
        cp_wait<0>();
        __syncthreads();
        {
            const uint32_t bufn = sbase + B_BUF0 + (uint32_t)((it + 1) & 1) * 17408u;
            const unsigned char* nsrc = (it < 127)
                ? g_wp + ((size_t)(it + 1) * 128 + wbase) * 256
                : g_wss + (size_t)wbase * 256;     // it=127 prefetches ss weights
            PREFETCH_B(nsrc, bufn);
        }

        float xr[4][3];
#pragma unroll
        for (int j = 0; j < 4; ++j) {
            const float* p = x + (size_t)(z0 + R0 + 8 * j) * NZ_COLS + MULV + 3 * it;
            xr[j][0] = __ldg(p); xr[j][1] = __ldg(p + 1); xr[j][2] = __ldg(p + 2);
        }

        float c[2][4][4];
#pragma unroll
        for (int mi = 0; mi < 2; ++mi)
#pragma unroll
            for (int nf = 0; nf < 4; ++nf)
#pragma unroll
                for (int e = 0; e < 4; ++e) c[mi][nf][e] = 0.f;

        const uint32_t bN0 = bufc + (uint32_t)n0 * 272u + boff;
        const uint32_t bN1 = bufc + (uint32_t)(n0 + 16) * 272u + boff;
        GEMM_F16(c, aH0, aH1, bN0, bN1);

#pragma unroll
        for (int mi = 0; mi < 2; ++mi)
#pragma unroll
            for (int e = 0; e < 4; ++e) {
                const int rj = 2 * mi + (e >> 1);
#pragma unroll
                for (int nf = 0; nf < 4; ++nf) {
                    const float t = c[mi][nf][e];
                    o[0][mi][nf][e] += t * xr[rj][0];
                    o[1][mi][nf][e] += t * xr[rj][1];
                    o[2][mi][nf][e] += t * xr[rj][2];
                }
            }
    }

    // =================== peeled tail: ss + vv terms ===================
    {
        float o2[2][4][4];               // out_s accumulators (tail-local)

        // ---- ss: B = g_wss (in buf0, parity it=128), prefetch vv into buf1
        cp_wait<0>();
        __syncthreads();
        PREFETCH_B(g_wvv + (size_t)wbase * 256, sbase + B_BUF0 + 17408u);
        {
            const uint32_t bufc = sbase + B_BUF0;    // 128&1 == 0
            const uint32_t bN0 = bufc + (uint32_t)n0 * 272u + boff;
            const uint32_t bN1 = bufc + (uint32_t)(n0 + 16) * 272u + boff;
            float c[2][4][4];
#pragma unroll
            for (int mi = 0; mi < 2; ++mi)
#pragma unroll
                for (int nf = 0; nf < 4; ++nf)
#pragma unroll
                    for (int e = 0; e < 4; ++e) c[mi][nf][e] = 0.f;
            GEMM_F16(c, aH0, aH1, bN0, bN1);
#pragma unroll
            for (int mi = 0; mi < 2; ++mi)
#pragma unroll
                for (int e = 0; e < 4; ++e) {
                    const int row = z0 + R0 + 16 * mi + 8 * (e >> 1);
#pragma unroll
                    for (int nf = 0; nf < 4; ++nf) {
                        const int u = wbase + n0 + 8 * nf + (lane & 3) * 2 + (e & 1);
                        o2[mi][nf][e] = PW_SS * __ldg(x + (size_t)row * NZ_COLS + u) * c[mi][nf][e];
                    }
                }
        }

        // ---- vv: 3 GEMMs sharing B = g_wvv (buf1)
        cp_wait<0>();
        __syncthreads();
        {
            const uint32_t bufc = sbase + B_BUF0 + 17408u;
            const uint32_t bN0 = bufc + (uint32_t)n0 * 272u + boff;
            const uint32_t bN1 = bufc + (uint32_t)(n0 + 16) * 272u + boff;
#pragma unroll 1
            for (int i = 0; i < 3; ++i) {
                const uint32_t aV0 = sbase + A_XV(i) + (uint32_t)m0 * 272u + aoff;
                const uint32_t aV1 = sbase + A_XV(i) + (uint32_t)(m0 + 16) * 272u + aoff;
                float c[2][4][4];
#pragma unroll
                for (int mi = 0; mi < 2; ++mi)
#pragma unroll
                    for (int nf = 0; nf < 4; ++nf)
#pragma unroll
                        for (int e = 0; e < 4; ++e) c[mi][nf][e] = 0.f;
                GEMM_F16(c, aV0, aV1, bN0, bN1);
#pragma unroll
                for (int mi = 0; mi < 2; ++mi)
#pragma unroll
                    for (int e = 0; e < 4; ++e) {
                        const int row = z0 + R0 + 16 * mi + 8 * (e >> 1);
#pragma unroll
                        for (int nf = 0; nf < 4; ++nf) {
                            const int u = wbase + n0 + 8 * nf + (lane & 3) * 2 + (e & 1);
                            o2[mi][nf][e] += PW_VV *
                                __ldg(x + (size_t)row * NZ_COLS + MULV + 3 * u + i) * c[mi][nf][e];
                        }
                    }
            }
        }

        // ---- final stores (out_s + out_v) ----
#pragma unroll
        for (int mi = 0; mi < 2; ++mi)
#pragma unroll
            for (int e = 0; e < 4; ++e) {
                const int row = z0 + R0 + 16 * mi + 8 * (e >> 1);
#pragma unroll
                for (int nf = 0; nf < 4; ++nf) {
                    const int w = wbase + n0 + 8 * nf + (lane & 3) * 2 + (e & 1);
                    float* p = out + (size_t)row * NZ_COLS + MULV + 3 * w;
                    p[0] = PW_SV * o[0][mi][nf][e];
                    p[1] = PW_SV * o[1][mi][nf][e];
                    p[2] = PW_SV * o[2][mi][nf][e];
                    out[(size_t)row * NZ_COLS + w] = o2[mi][nf][e];
                }
            }
    }
}

// ---------------------------------------------------------------------------
extern "C" void kernel_launch(void* const* d_in, const int* in_sizes, int n_in,
                              void* d_out, int out_size)
{
    const float* x    = (const float*)d_in[0];
    const float* w_ss = (const float*)d_in[1];
    const float* w_sv = (const float*)d_in[2];
    const float* w_vv = (const float*)d_in[3];
    float* out = (float*)d_out;

    const int n = in_sizes[0] / NZ_COLS;           // 8192
    const int pack_smem = 128 * 133 * 4;           // ~68 KB

    cudaFuncSetAttribute(pack_b_kernel, cudaFuncAttributeMaxDynamicSharedMemorySize, pack_smem);
    cudaFuncSetAttribute(sv_mma_kernel, cudaFuncAttributeMaxDynamicSharedMemorySize, SMEM_MAIN);

    pack_b_kernel<<<130, 256, pack_smem>>>(w_sv, w_ss, w_vv);
    sv_mma_kernel<<<dim3(n / 128, 2), 256, SMEM_MAIN>>>(x, out);
}

// round 14
// speedup vs baseline: 2.1280x; 1.3139x over previous
#include <cuda_runtime.h>
#include <cuda_fp16.h>
#include <cstdint>

#define MULV    128
#define NZ_COLS 512
#define PW_SS 0.0625f
#define PW_VV 0.03608439182435161f
#define PW_SV 0.0078125f

// Packed weights (fp16): g_wp[v][w][u] (4.2 MB), g_wss[u][v], g_wvv[u][v]
__device__ unsigned char g_wp[128u * 128u * 256u];
__device__ unsigned char g_wss[128u * 256u];
__device__ unsigned char g_wvv[128u * 256u];

// ---------------- helpers ----------------
__device__ __forceinline__ uint32_t smem_u32(const void* p) {
    uint32_t a;
    asm("{ .reg .u64 t; cvta.to.shared.u64 t, %1; cvt.u32.u64 %0, t; }" : "=r"(a) : "l"(p));
    return a;
}
__device__ __forceinline__ void ldsm4(uint32_t r[4], uint32_t addr) {
    asm volatile("ldmatrix.sync.aligned.m8n8.x4.shared.b16 {%0,%1,%2,%3}, [%4];"
                 : "=r"(r[0]), "=r"(r[1]), "=r"(r[2]), "=r"(r[3]) : "r"(addr));
}
__device__ __forceinline__ void mma_f16(float c[4], const uint32_t a[4],
                                        uint32_t b0, uint32_t b1) {
    asm volatile("mma.sync.aligned.m16n8k16.row.col.f32.f16.f16.f32 "
                 "{%0,%1,%2,%3}, {%4,%5,%6,%7}, {%8,%9}, {%0,%1,%2,%3};"
                 : "+f"(c[0]), "+f"(c[1]), "+f"(c[2]), "+f"(c[3])
                 : "r"(a[0]), "r"(a[1]), "r"(a[2]), "r"(a[3]), "r"(b0), "r"(b1));
}
__device__ __forceinline__ void cp16(uint32_t sdst, const void* gsrc) {
    asm volatile("cp.async.cg.shared.global [%0], [%1], 16;" :: "r"(sdst), "l"(gsrc));
}
__device__ __forceinline__ void cp_commit() { asm volatile("cp.async.commit_group;"); }
template <int N> __device__ __forceinline__ void cp_wait() {
    asm volatile("cp.async.wait_group %0;" :: "n"(N));
}
__device__ __forceinline__ uint32_t pack_h2(float f0, float f1) {
    __half h0 = __float2half_rn(f0), h1 = __float2half_rn(f1);
    return (uint32_t)__half_as_ushort(h0) | ((uint32_t)__half_as_ushort(h1) << 16);
}

// ---------------------------------------------------------------------------
// Pack: blocks 0-127: w_sv[u][v][w] -> g_wp[v][w][u] fp16.
//       block 128: w_ss -> g_wss. block 129: w_vv -> g_wvv.
// ---------------------------------------------------------------------------
__global__ void pack_b_kernel(const float* __restrict__ wsv,
                              const float* __restrict__ wss,
                              const float* __restrict__ wvv) {
    extern __shared__ float tile[];              // [128 w][133]
    const int tid = threadIdx.x;
    if (blockIdx.x >= 128) {
        const float* src = (blockIdx.x == 128) ? wss : wvv;
        uint32_t* dst = (uint32_t*)((blockIdx.x == 128) ? g_wss : g_wvv);
        for (int j = tid; j < 8192; j += 256)
            dst[j] = pack_h2(src[2 * j], src[2 * j + 1]);
        return;
    }
    const int v = blockIdx.x;
    for (int idx = tid; idx < 16384; idx += 256) {
        const int u = idx >> 7, w = idx & 127;
        tile[w * 133 + u] = wsv[(size_t)u * 16384 + (size_t)v * 128 + w];
    }
    __syncthreads();
    for (int j = tid; j < 8192; j += 256) {
        const int w = j >> 6, u0 = (j & 63) * 2;
        uint32_t* dst = (uint32_t*)(g_wp + ((size_t)v * 128 + w) * 256);
        dst[u0 >> 1] = pack_h2(tile[w * 133 + u0], tile[w * 133 + u0 + 1]);
    }
}

// ---------------------------------------------------------------------------
// Fused kernel: grid (64 z-tiles, 2 halves), 256 threads (8 warps, m32n32).
// v processed in PAIRS sharing A-fragment ldsm loads (A is v-invariant):
// per k-step 2 A-ldsm + 4 B-ldsm -> 16 mma into two accumulator sets.
// One __syncthreads + one cp group per pair; 4-slot B ring.
// Epilogue xv read as half2 from A_XV smem tiles (v0,v1 adjacent).
// SMEM: A_xs @0, A_xv0/1/2 @34816/69632/104448 (128x272B each),
//       B ring 4 x 17408B @139264. Total 208896.
// ---------------------------------------------------------------------------
#define A_XV(i)  (34816u * (1u + (i)))
#define B_RING   139264u
#define B_SLOT(v) (B_RING + (uint32_t)((v) & 3) * 17408u)
#define SMEM_MAIN 208896

__global__ __launch_bounds__(256, 1) void sv_mma_kernel(
    const float* __restrict__ x, float* __restrict__ out)
{
    extern __shared__ unsigned char smem[];
    const uint32_t sbase = smem_u32(smem);

    const int tid = threadIdx.x;
    const int lane = tid & 31;
    const int warp = tid >> 5;
    const int m0 = (warp >> 1) * 32;
    const int n0 = (warp & 1) * 32;
    const int z0 = blockIdx.x * 128;
    const int wbase = blockIdx.y * 64;   // w-half AND u-half

    // ---- A_xs tile: fp16, stride 272B ----
    {
        const int row = tid >> 1, uh = (tid & 1) * 64;
        const float4* src = (const float4*)(x + (size_t)(z0 + row) * NZ_COLS + uh);
        uint32_t* dst = (uint32_t*)(smem + row * 272u + uh * 2u);
#pragma unroll
        for (int j = 0; j < 16; ++j) {
            float4 f = src[j];
            dst[2 * j]     = pack_h2(f.x, f.y);
            dst[2 * j + 1] = pack_h2(f.z, f.w);
        }
    }
    // ---- A_xv tiles: de-interleave xv components into 3 fp16 tiles ----
    {
        const int row = tid >> 1;
        const int c0 = (tid & 1) * 192;
        const float4* src = (const float4*)(x + (size_t)(z0 + row) * NZ_COLS + MULV + c0);
#pragma unroll 8
        for (int j = 0; j < 48; ++j) {
            float4 f = src[j];
            float vals[4] = {f.x, f.y, f.z, f.w};
#pragma unroll
            for (int t = 0; t < 4; ++t) {
                int cc = c0 + 4 * j + t;
                int v = cc / 3, i = cc - 3 * v;
                *(__half*)(smem + A_XV(i) + row * 272u + v * 2u) = __float2half_rn(vals[t]);
            }
        }
    }

    const uint32_t aoff = ((lane & 7) + ((lane >> 3) & 1) * 8) * 272u + ((lane >> 4) & 1) * 16u;
    const uint32_t boff = ((lane & 7) + ((lane >> 4) & 1) * 8) * 272u + ((lane >> 3) & 1) * 16u;

// copy one 16KB B tile (64 rows x 256B) into a ring slot: 4 cp16/thread
#define PREFETCH_ONE(gsrc, bufaddr) do { \
    const unsigned char* _g = (gsrc); \
    _Pragma("unroll") \
    for (int i = 0; i < 4; ++i) { \
        int c = tid + 256 * i; \
        int r = c >> 4, ch = c & 15; \
        cp16((bufaddr) + (uint32_t)r * 272u + (uint32_t)ch * 16u, \
             _g + (size_t)r * 256 + ch * 16); \
    } \
} while (0)

#define GEMM_F16(cc, aB0, aB1, bN0, bN1) do { \
    _Pragma("unroll") \
    for (int k0 = 0; k0 < 128; k0 += 16) { \
        const uint32_t ko = (uint32_t)k0 * 2u; \
        uint32_t a0[4], a1[4], b0[4], b1[4]; \
        ldsm4(a0, (aB0) + ko); \
        ldsm4(a1, (aB1) + ko); \
        ldsm4(b0, (bN0) + ko); \
        ldsm4(b1, (bN1) + ko); \
        mma_f16((cc)[0][0], a0, b0[0], b0[1]); \
        mma_f16((cc)[0][1], a0, b0[2], b0[3]); \
        mma_f16((cc)[0][2], a0, b1[0], b1[1]); \
        mma_f16((cc)[0][3], a0, b1[2], b1[3]); \
        mma_f16((cc)[1][0], a1, b0[0], b0[1]); \
        mma_f16((cc)[1][1], a1, b0[2], b0[3]); \
        mma_f16((cc)[1][2], a1, b1[0], b1[1]); \
        mma_f16((cc)[1][3], a1, b1[2], b1[3]); \
    } \
} while (0)

    // prefetch pair 0 into slots 0,1
    PREFETCH_ONE(g_wp + ((size_t)0 * 128 + wbase) * 256, sbase + B_SLOT(0));
    PREFETCH_ONE(g_wp + ((size_t)1 * 128 + wbase) * 256, sbase + B_SLOT(1));
    cp_commit();

    float o[3][2][4][4];                 // out_v accumulators (persistent)
#pragma unroll
    for (int mi = 0; mi < 2; ++mi)
#pragma unroll
        for (int nf = 0; nf < 4; ++nf)
#pragma unroll
            for (int e = 0; e < 4; ++e) {
                o[0][mi][nf][e] = 0.f; o[1][mi][nf][e] = 0.f; o[2][mi][nf][e] = 0.f;
            }

    const int R0 = m0 + (lane >> 2);
    const uint32_t aH0 = sbase + (uint32_t)m0 * 272u + aoff;
    const uint32_t aH1 = sbase + (uint32_t)(m0 + 16) * 272u + aoff;

    // =================== paired v-loop ===================
    for (int p = 0; p < 64; ++p) {
        const int v0 = 2 * p;
        cp_wait<0>();
        __syncthreads();
        // prefetch next pair (or ss/vv weights on the last pair)
        if (p < 63) {
            PREFETCH_ONE(g_wp + ((size_t)(v0 + 2) * 128 + wbase) * 256, sbase + B_SLOT(v0 + 2));
            PREFETCH_ONE(g_wp + ((size_t)(v0 + 3) * 128 + wbase) * 256, sbase + B_SLOT(v0 + 3));
        } else {
            PREFETCH_ONE(g_wss + (size_t)wbase * 256, sbase + B_SLOT(0));
            PREFETCH_ONE(g_wvv + (size_t)wbase * 256, sbase + B_SLOT(1));
        }
        cp_commit();

        float c0[2][4][4], c1[2][4][4];
#pragma unroll
        for (int mi = 0; mi < 2; ++mi)
#pragma unroll
            for (int nf = 0; nf < 4; ++nf)
#pragma unroll
                for (int e = 0; e < 4; ++e) { c0[mi][nf][e] = 0.f; c1[mi][nf][e] = 0.f; }

        const uint32_t bu0 = sbase + B_SLOT(v0);
        const uint32_t bu1 = sbase + B_SLOT(v0 + 1);
        const uint32_t b0N0 = bu0 + (uint32_t)n0 * 272u + boff;
        const uint32_t b0N1 = bu0 + (uint32_t)(n0 + 16) * 272u + boff;
        const uint32_t b1N0 = bu1 + (uint32_t)n0 * 272u + boff;
        const uint32_t b1N1 = bu1 + (uint32_t)(n0 + 16) * 272u + boff;

        // fused pair GEMM: A-frags loaded once per k-step, used for both v's
#pragma unroll
        for (int k0 = 0; k0 < 128; k0 += 16) {
            const uint32_t ko = (uint32_t)k0 * 2u;
            uint32_t a0[4], a1[4], p0[4], p1[4], q0[4], q1[4];
            ldsm4(a0, aH0 + ko);
            ldsm4(a1, aH1 + ko);
            ldsm4(p0, b0N0 + ko);
            ldsm4(p1, b0N1 + ko);
            ldsm4(q0, b1N0 + ko);
            ldsm4(q1, b1N1 + ko);
            mma_f16(c0[0][0], a0, p0[0], p0[1]);
            mma_f16(c0[0][1], a0, p0[2], p0[3]);
            mma_f16(c0[0][2], a0, p1[0], p1[1]);
            mma_f16(c0[0][3], a0, p1[2], p1[3]);
            mma_f16(c1[0][0], a0, q0[0], q0[1]);
            mma_f16(c1[0][1], a0, q0[2], q0[3]);
            mma_f16(c1[0][2], a0, q1[0], q1[1]);
            mma_f16(c1[0][3], a0, q1[2], q1[3]);
            mma_f16(c0[1][0], a1, p0[0], p0[1]);
            mma_f16(c0[1][1], a1, p0[2], p0[3]);
            mma_f16(c0[1][2], a1, p1[0], p1[1]);
            mma_f16(c0[1][3], a1, p1[2], p1[3]);
            mma_f16(c1[1][0], a1, q0[0], q0[1]);
            mma_f16(c1[1][1], a1, q0[2], q0[3]);
            mma_f16(c1[1][2], a1, q1[0], q1[1]);
            mma_f16(c1[1][3], a1, q1[2], q1[3]);
        }

        // epilogue: xv for (v0, v0+1) read as half2 from A_XV tiles
#pragma unroll
        for (int mi = 0; mi < 2; ++mi)
#pragma unroll
            for (int e = 0; e < 4; ++e) {
                const int rj = 2 * mi + (e >> 1);
                const uint32_t roff = (uint32_t)(R0 + 8 * rj) * 272u + (uint32_t)v0 * 2u;
                float x00, x01, x10, x11, x20, x21;
                {
                    __half2 h0 = *(const __half2*)(smem + A_XV(0) + roff);
                    __half2 h1 = *(const __half2*)(smem + A_XV(1) + roff);
                    __half2 h2 = *(const __half2*)(smem + A_XV(2) + roff);
                    float2 f0 = __half22float2(h0);
                    float2 f1 = __half22float2(h1);
                    float2 f2 = __half22float2(h2);
                    x00 = f0.x; x01 = f0.y;
                    x10 = f1.x; x11 = f1.y;
                    x20 = f2.x; x21 = f2.y;
                }
#pragma unroll
                for (int nf = 0; nf < 4; ++nf) {
                    const float t0 = c0[mi][nf][e];
                    const float t1 = c1[mi][nf][e];
                    o[0][mi][nf][e] += t0 * x00 + t1 * x01;
                    o[1][mi][nf][e] += t0 * x10 + t1 * x11;
                    o[2][mi][nf][e] += t0 * x20 + t1 * x21;
                }
            }
    }

    // =================== peeled tail: ss + vv terms ===================
    {
        float o2[2][4][4];

        cp_wait<0>();
        __syncthreads();
        // ---- ss: B = g_wss (slot 0)
        {
            const uint32_t bufc = sbase + B_SLOT(0);
            const uint32_t bN0 = bufc + (uint32_t)n0 * 272u + boff;
            const uint32_t bN1 = bufc + (uint32_t)(n0 + 16) * 272u + boff;
            float c[2][4][4];
#pragma unroll
            for (int mi = 0; mi < 2; ++mi)
#pragma unroll
                for (int nf = 0; nf < 4; ++nf)
#pragma unroll
                    for (int e = 0; e < 4; ++e) c[mi][nf][e] = 0.f;
            GEMM_F16(c, aH0, aH1, bN0, bN1);
#pragma unroll
            for (int mi = 0; mi < 2; ++mi)
#pragma unroll
                for (int e = 0; e < 4; ++e) {
                    const int row = z0 + R0 + 16 * mi + 8 * (e >> 1);
#pragma unroll
                    for (int nf = 0; nf < 4; ++nf) {
                        const int u = wbase + n0 + 8 * nf + (lane & 3) * 2 + (e & 1);
                        o2[mi][nf][e] = PW_SS * __ldg(x + (size_t)row * NZ_COLS + u) * c[mi][nf][e];
                    }
                }
        }

        // ---- vv: 3 GEMMs sharing B = g_wvv (slot 1)
        {
            const uint32_t bufc = sbase + B_SLOT(1);
            const uint32_t bN0 = bufc + (uint32_t)n0 * 272u + boff;
            const uint32_t bN1 = bufc + (uint32_t)(n0 + 16) * 272u + boff;
#pragma unroll 1
            for (int i = 0; i < 3; ++i) {
                const uint32_t aV0 = sbase + A_XV(i) + (uint32_t)m0 * 272u + aoff;
                const uint32_t aV1 = sbase + A_XV(i) + (uint32_t)(m0 + 16) * 272u + aoff;
                float c[2][4][4];
#pragma unroll
                for (int mi = 0; mi < 2; ++mi)
#pragma unroll
                    for (int nf = 0; nf < 4; ++nf)
#pragma unroll
                        for (int e = 0; e < 4; ++e) c[mi][nf][e] = 0.f;
                GEMM_F16(c, aV0, aV1, bN0, bN1);
#pragma unroll
                for (int mi = 0; mi < 2; ++mi)
#pragma unroll
                    for (int e = 0; e < 4; ++e) {
                        const int row = z0 + R0 + 16 * mi + 8 * (e >> 1);
#pragma unroll
                        for (int nf = 0; nf < 4; ++nf) {
                            const int u = wbase + n0 + 8 * nf + (lane & 3) * 2 + (e & 1);
                            o2[mi][nf][e] += PW_VV *
                                __ldg(x + (size_t)row * NZ_COLS + MULV + 3 * u + i) * c[mi][nf][e];
                        }
                    }
            }
        }

        // ---- final stores (out_s + out_v) ----
#pragma unroll
        for (int mi = 0; mi < 2; ++mi)
#pragma unroll
            for (int e = 0; e < 4; ++e) {
                const int row = z0 + R0 + 16 * mi + 8 * (e >> 1);
#pragma unroll
                for (int nf = 0; nf < 4; ++nf) {
                    const int w = wbase + n0 + 8 * nf + (lane & 3) * 2 + (e & 1);
                    float* p = out + (size_t)row * NZ_COLS + MULV + 3 * w;
                    p[0] = PW_SV * o[0][mi][nf][e];
                    p[1] = PW_SV * o[1][mi][nf][e];
                    p[2] = PW_SV * o[2][mi][nf][e];
                    out[(size_t)row * NZ_COLS + w] = o2[mi][nf][e];
                }
            }
    }
}

// ---------------------------------------------------------------------------
extern "C" void kernel_launch(void* const* d_in, const int* in_sizes, int n_in,
                              void* d_out, int out_size)
{
    const float* x    = (const float*)d_in[0];
    const float* w_ss = (const float*)d_in[1];
    const float* w_sv = (const float*)d_in[2];
    const float* w_vv = (const float*)d_in[3];
    float* out = (float*)d_out;

    const int n = in_sizes[0] / NZ_COLS;           // 8192
    const int pack_smem = 128 * 133 * 4;           // ~68 KB

    cudaFuncSetAttribute(pack_b_kernel, cudaFuncAttributeMaxDynamicSharedMemorySize, pack_smem);
    cudaFuncSetAttribute(sv_mma_kernel, cudaFuncAttributeMaxDynamicSharedMemorySize, SMEM_MAIN);

    pack_b_kernel<<<130, 256, pack_smem>>>(w_sv, w_ss, w_vv);
    sv_mma_kernel<<<dim3(n / 128, 2), 256, SMEM_MAIN>>>(x, out);
}

// round 15
// speedup vs baseline: 2.2111x; 1.0391x over previous
#include <cuda_runtime.h>
#include <cuda_fp16.h>
#include <cstdint>

#define MULV    128
#define NZ_COLS 512
#define PW_SS 0.0625f
#define PW_VV 0.03608439182435161f
#define PW_SV 0.0078125f

// Packed weights (fp16): g_wp[v][w][u] (4.2 MB), g_wss[u][v], g_wvv[u][v]
__device__ unsigned char g_wp[128u * 128u * 256u];
__device__ unsigned char g_wss[128u * 256u];
__device__ unsigned char g_wvv[128u * 256u];

// ---------------- helpers ----------------
__device__ __forceinline__ uint32_t smem_u32(const void* p) {
    uint32_t a;
    asm("{ .reg .u64 t; cvta.to.shared.u64 t, %1; cvt.u32.u64 %0, t; }" : "=r"(a) : "l"(p));
    return a;
}
__device__ __forceinline__ void ldsm4(uint32_t r[4], uint32_t addr) {
    asm volatile("ldmatrix.sync.aligned.m8n8.x4.shared.b16 {%0,%1,%2,%3}, [%4];"
                 : "=r"(r[0]), "=r"(r[1]), "=r"(r[2]), "=r"(r[3]) : "r"(addr));
}
__device__ __forceinline__ void mma_f16(float c[4], const uint32_t a[4],
                                        uint32_t b0, uint32_t b1) {
    asm volatile("mma.sync.aligned.m16n8k16.row.col.f32.f16.f16.f32 "
                 "{%0,%1,%2,%3}, {%4,%5,%6,%7}, {%8,%9}, {%0,%1,%2,%3};"
                 : "+f"(c[0]), "+f"(c[1]), "+f"(c[2]), "+f"(c[3])
                 : "r"(a[0]), "r"(a[1]), "r"(a[2]), "r"(a[3]), "r"(b0), "r"(b1));
}
__device__ __forceinline__ void cp16(uint32_t sdst, const void* gsrc) {
    asm volatile("cp.async.cg.shared.global [%0], [%1], 16;" :: "r"(sdst), "l"(gsrc));
}
__device__ __forceinline__ void cp_commit() { asm volatile("cp.async.commit_group;"); }
template <int N> __device__ __forceinline__ void cp_wait() {
    asm volatile("cp.async.wait_group %0;" :: "n"(N));
}
__device__ __forceinline__ uint32_t pack_h2(float f0, float f1) {
    __half h0 = __float2half_rn(f0), h1 = __float2half_rn(f1);
    return (uint32_t)__half_as_ushort(h0) | ((uint32_t)__half_as_ushort(h1) << 16);
}

// ---------------------------------------------------------------------------
// Pack: blocks 0-127: w_sv[u][v][w] -> g_wp[v][w][u] fp16.
//       block 128: w_ss -> g_wss. block 129: w_vv -> g_wvv.
// ---------------------------------------------------------------------------
__global__ void pack_b_kernel(const float* __restrict__ wsv,
                              const float* __restrict__ wss,
                              const float* __restrict__ wvv) {
    extern __shared__ float tile[];              // [128 w][133]
    const int tid = threadIdx.x;
    if (blockIdx.x >= 128) {
        const float* src = (blockIdx.x == 128) ? wss : wvv;
        uint32_t* dst = (uint32_t*)((blockIdx.x == 128) ? g_wss : g_wvv);
        for (int j = tid; j < 8192; j += 256)
            dst[j] = pack_h2(src[2 * j], src[2 * j + 1]);
        return;
    }
    const int v = blockIdx.x;
    for (int idx = tid; idx < 16384; idx += 256) {
        const int u = idx >> 7, w = idx & 127;
        tile[w * 133 + u] = wsv[(size_t)u * 16384 + (size_t)v * 128 + w];
    }
    __syncthreads();
    for (int j = tid; j < 8192; j += 256) {
        const int w = j >> 6, u0 = (j & 63) * 2;
        uint32_t* dst = (uint32_t*)(g_wp + ((size_t)v * 128 + w) * 256);
        dst[u0 >> 1] = pack_h2(tile[w * 133 + u0], tile[w * 133 + u0 + 1]);
    }
}

// ---------------------------------------------------------------------------
// Fused kernel: grid (64 z-tiles, 2 halves), 256 threads (8 warps, m32n32).
// A (xs) fragments held ENTIRELY in registers (areg[2][8][4], loaded once):
// the v-loop does only 2 B-ldsm + 8 mma per k-step, single v per iteration.
// Epilogue xv read as fp16 from A_XV smem tiles. Peeled ss+vv tail.
// SMEM: A_xs @0, A_xv0/1/2 @34816/69632/104448 (128x272B each),
//       B ring 4 x 17408B @139264. Total 208896.
// ---------------------------------------------------------------------------
#define A_XV(i)  (34816u * (1u + (i)))
#define B_RING   139264u
#define B_SLOT(v) (B_RING + (uint32_t)((v) & 3) * 17408u)
#define SMEM_MAIN 208896

__global__ __launch_bounds__(256, 1) void sv_mma_kernel(
    const float* __restrict__ x, float* __restrict__ out)
{
    extern __shared__ unsigned char smem[];
    const uint32_t sbase = smem_u32(smem);

    const int tid = threadIdx.x;
    const int lane = tid & 31;
    const int warp = tid >> 5;
    const int m0 = (warp >> 1) * 32;
    const int n0 = (warp & 1) * 32;
    const int z0 = blockIdx.x * 128;
    const int wbase = blockIdx.y * 64;   // w-half AND u-half

    // ---- A_xs tile: fp16, stride 272B ----
    {
        const int row = tid >> 1, uh = (tid & 1) * 64;
        const float4* src = (const float4*)(x + (size_t)(z0 + row) * NZ_COLS + uh);
        uint32_t* dst = (uint32_t*)(smem + row * 272u + uh * 2u);
#pragma unroll
        for (int j = 0; j < 16; ++j) {
            float4 f = src[j];
            dst[2 * j]     = pack_h2(f.x, f.y);
            dst[2 * j + 1] = pack_h2(f.z, f.w);
        }
    }
    // ---- A_xv tiles: de-interleave xv components into 3 fp16 tiles ----
    {
        const int row = tid >> 1;
        const int c0 = (tid & 1) * 192;
        const float4* src = (const float4*)(x + (size_t)(z0 + row) * NZ_COLS + MULV + c0);
#pragma unroll 8
        for (int j = 0; j < 48; ++j) {
            float4 f = src[j];
            float vals[4] = {f.x, f.y, f.z, f.w};
#pragma unroll
            for (int t = 0; t < 4; ++t) {
                int cc = c0 + 4 * j + t;
                int v = cc / 3, i = cc - 3 * v;
                *(__half*)(smem + A_XV(i) + row * 272u + v * 2u) = __float2half_rn(vals[t]);
            }
        }
    }

    const uint32_t aoff = ((lane & 7) + ((lane >> 3) & 1) * 8) * 272u + ((lane >> 4) & 1) * 16u;
    const uint32_t boff = ((lane & 7) + ((lane >> 4) & 1) * 8) * 272u + ((lane >> 3) & 1) * 16u;

// copy one 16KB B tile (64 rows x 256B) into a ring slot: 4 cp16/thread
#define PREFETCH_ONE(gsrc, bufaddr) do { \
    const unsigned char* _g = (gsrc); \
    _Pragma("unroll") \
    for (int i = 0; i < 4; ++i) { \
        int c = tid + 256 * i; \
        int r = c >> 4, ch = c & 15; \
        cp16((bufaddr) + (uint32_t)r * 272u + (uint32_t)ch * 16u, \
             _g + (size_t)r * 256 + ch * 16); \
    } \
    cp_commit(); \
} while (0)

    // prefetch v=0,1 (separate groups)
    PREFETCH_ONE(g_wp + (size_t)wbase * 256, sbase + B_SLOT(0));
    PREFETCH_ONE(g_wp + ((size_t)128 + wbase) * 256, sbase + B_SLOT(1));

    __syncthreads();     // A tiles visible

    // ---- load ALL A fragments into registers (v-invariant) ----
    uint32_t areg[2][8][4];
    {
        const uint32_t aH0 = sbase + (uint32_t)m0 * 272u + aoff;
        const uint32_t aH1 = sbase + (uint32_t)(m0 + 16) * 272u + aoff;
#pragma unroll
        for (int ks = 0; ks < 8; ++ks) {
            ldsm4(areg[0][ks], aH0 + (uint32_t)ks * 32u);
            ldsm4(areg[1][ks], aH1 + (uint32_t)ks * 32u);
        }
    }

    float o[3][2][4][4];                 // out_v accumulators (persistent)
#pragma unroll
    for (int mi = 0; mi < 2; ++mi)
#pragma unroll
        for (int nf = 0; nf < 4; ++nf)
#pragma unroll
            for (int e = 0; e < 4; ++e) {
                o[0][mi][nf][e] = 0.f; o[1][mi][nf][e] = 0.f; o[2][mi][nf][e] = 0.f;
            }

    const int R0 = m0 + (lane >> 2);

    // =================== single-v loop, A in registers ===================
    for (int v = 0; v < 128; ++v) {
        cp_wait<1>();                    // group for this v complete
        __syncthreads();
        if (v < 126) {
            PREFETCH_ONE(g_wp + ((size_t)(v + 2) * 128 + wbase) * 256, sbase + B_SLOT(v + 2));
        } else if (v == 126) {
            PREFETCH_ONE(g_wss + (size_t)wbase * 256, sbase + B_SLOT(0));
        } else {
            PREFETCH_ONE(g_wvv + (size_t)wbase * 256, sbase + B_SLOT(1));
        }

        float c[2][4][4];
#pragma unroll
        for (int mi = 0; mi < 2; ++mi)
#pragma unroll
            for (int nf = 0; nf < 4; ++nf)
#pragma unroll
                for (int e = 0; e < 4; ++e) c[mi][nf][e] = 0.f;

        const uint32_t bu = sbase + B_SLOT(v);
        const uint32_t bN0 = bu + (uint32_t)n0 * 272u + boff;
        const uint32_t bN1 = bu + (uint32_t)(n0 + 16) * 272u + boff;

#pragma unroll
        for (int ks = 0; ks < 8; ++ks) {
            const uint32_t ko = (uint32_t)ks * 32u;
            uint32_t b0[4], b1[4];
            ldsm4(b0, bN0 + ko);
            ldsm4(b1, bN1 + ko);
            mma_f16(c[0][0], areg[0][ks], b0[0], b0[1]);
            mma_f16(c[0][1], areg[0][ks], b0[2], b0[3]);
            mma_f16(c[0][2], areg[0][ks], b1[0], b1[1]);
            mma_f16(c[0][3], areg[0][ks], b1[2], b1[3]);
            mma_f16(c[1][0], areg[1][ks], b0[0], b0[1]);
            mma_f16(c[1][1], areg[1][ks], b0[2], b0[3]);
            mma_f16(c[1][2], areg[1][ks], b1[0], b1[1]);
            mma_f16(c[1][3], areg[1][ks], b1[2], b1[3]);
        }

        // epilogue: xv[z, v, i] read as fp16 from A_XV smem tiles
#pragma unroll
        for (int mi = 0; mi < 2; ++mi)
#pragma unroll
            for (int e = 0; e < 4; ++e) {
                const int rj = 2 * mi + (e >> 1);
                const uint32_t roff = (uint32_t)(R0 + 8 * rj) * 272u + (uint32_t)v * 2u;
                const float x0 = __half2float(*(const __half*)(smem + A_XV(0) + roff));
                const float x1 = __half2float(*(const __half*)(smem + A_XV(1) + roff));
                const float x2 = __half2float(*(const __half*)(smem + A_XV(2) + roff));
#pragma unroll
                for (int nf = 0; nf < 4; ++nf) {
                    const float t = c[mi][nf][e];
                    o[0][mi][nf][e] += t * x0;
                    o[1][mi][nf][e] += t * x1;
                    o[2][mi][nf][e] += t * x2;
                }
            }
    }

    // =================== peeled tail: ss + vv terms ===================
    {
        float o2[2][4][4];

        // ---- ss: B = g_wss (slot 0); A from registers
        cp_wait<1>();
        __syncthreads();
        {
            const uint32_t bu = sbase + B_SLOT(0);
            const uint32_t bN0 = bu + (uint32_t)n0 * 272u + boff;
            const uint32_t bN1 = bu + (uint32_t)(n0 + 16) * 272u + boff;
            float c[2][4][4];
#pragma unroll
            for (int mi = 0; mi < 2; ++mi)
#pragma unroll
                for (int nf = 0; nf < 4; ++nf)
#pragma unroll
                    for (int e = 0; e < 4; ++e) c[mi][nf][e] = 0.f;
#pragma unroll
            for (int ks = 0; ks < 8; ++ks) {
                const uint32_t ko = (uint32_t)ks * 32u;
                uint32_t b0[4], b1[4];
                ldsm4(b0, bN0 + ko);
                ldsm4(b1, bN1 + ko);
                mma_f16(c[0][0], areg[0][ks], b0[0], b0[1]);
                mma_f16(c[0][1], areg[0][ks], b0[2], b0[3]);
                mma_f16(c[0][2], areg[0][ks], b1[0], b1[1]);
                mma_f16(c[0][3], areg[0][ks], b1[2], b1[3]);
                mma_f16(c[1][0], areg[1][ks], b0[0], b0[1]);
                mma_f16(c[1][1], areg[1][ks], b0[2], b0[3]);
                mma_f16(c[1][2], areg[1][ks], b1[0], b1[1]);
                mma_f16(c[1][3], areg[1][ks], b1[2], b1[3]);
            }
#pragma unroll
            for (int mi = 0; mi < 2; ++mi)
#pragma unroll
                for (int e = 0; e < 4; ++e) {
                    const int row = z0 + R0 + 16 * mi + 8 * (e >> 1);
#pragma unroll
                    for (int nf = 0; nf < 4; ++nf) {
                        const int u = wbase + n0 + 8 * nf + (lane & 3) * 2 + (e & 1);
                        o2[mi][nf][e] = PW_SS * __ldg(x + (size_t)row * NZ_COLS + u) * c[mi][nf][e];
                    }
                }
        }

        // ---- vv: 3 GEMMs sharing B = g_wvv (slot 1); A from A_XV smem
        cp_wait<0>();
        __syncthreads();
        {
            const uint32_t bu = sbase + B_SLOT(1);
            const uint32_t bN0 = bu + (uint32_t)n0 * 272u + boff;
            const uint32_t bN1 = bu + (uint32_t)(n0 + 16) * 272u + boff;
#pragma unroll 1
            for (int i = 0; i < 3; ++i) {
                const uint32_t aV0 = sbase + A_XV(i) + (uint32_t)m0 * 272u + aoff;
                const uint32_t aV1 = sbase + A_XV(i) + (uint32_t)(m0 + 16) * 272u + aoff;
                float c[2][4][4];
#pragma unroll
                for (int mi = 0; mi < 2; ++mi)
#pragma unroll
                    for (int nf = 0; nf < 4; ++nf)
#pragma unroll
                        for (int e = 0; e < 4; ++e) c[mi][nf][e] = 0.f;
#pragma unroll
                for (int ks = 0; ks < 8; ++ks) {
                    const uint32_t ko = (uint32_t)ks * 32u;
                    uint32_t a0[4], a1[4], b0[4], b1[4];
                    ldsm4(a0, aV0 + ko);
                    ldsm4(a1, aV1 + ko);
                    ldsm4(b0, bN0 + ko);
                    ldsm4(b1, bN1 + ko);
                    mma_f16(c[0][0], a0, b0[0], b0[1]);
                    mma_f16(c[0][1], a0, b0[2], b0[3]);
                    mma_f16(c[0][2], a0, b1[0], b1[1]);
                    mma_f16(c[0][3], a0, b1[2], b1[3]);
                    mma_f16(c[1][0], a1, b0[0], b0[1]);
                    mma_f16(c[1][1], a1, b0[2], b0[3]);
                    mma_f16(c[1][2], a1, b1[0], b1[1]);
                    mma_f16(c[1][3], a1, b1[2], b1[3]);
                }
#pragma unroll
                for (int mi = 0; mi < 2; ++mi)
#pragma unroll
                    for (int e = 0; e < 4; ++e) {
                        const int row = z0 + R0 + 16 * mi + 8 * (e >> 1);
#pragma unroll
                        for (int nf = 0; nf < 4; ++nf) {
                            const int u = wbase + n0 + 8 * nf + (lane & 3) * 2 + (e & 1);
                            o2[mi][nf][e] += PW_VV *
                                __ldg(x + (size_t)row * NZ_COLS + MULV + 3 * u + i) * c[mi][nf][e];
                        }
                    }
            }
        }

        // ---- final stores (out_s + out_v) ----
#pragma unroll
        for (int mi = 0; mi < 2; ++mi)
#pragma unroll
            for (int e = 0; e < 4; ++e) {
                const int row = z0 + R0 + 16 * mi + 8 * (e >> 1);
#pragma unroll
                for (int nf = 0; nf < 4; ++nf) {
                    const int w = wbase + n0 + 8 * nf + (lane & 3) * 2 + (e & 1);
                    float* p = out + (size_t)row * NZ_COLS + MULV + 3 * w;
                    p[0] = PW_SV * o[0][mi][nf][e];
                    p[1] = PW_SV * o[1][mi][nf][e];
                    p[2] = PW_SV * o[2][mi][nf][e];
                    out[(size_t)row * NZ_COLS + w] = o2[mi][nf][e];
                }
            }
    }
}

// ---------------------------------------------------------------------------
extern "C" void kernel_launch(void* const* d_in, const int* in_sizes, int n_in,
                              void* d_out, int out_size)
{
    const float* x    = (const float*)d_in[0];
    const float* w_ss = (const float*)d_in[1];
    const float* w_sv = (const float*)d_in[2];
    const float* w_vv = (const float*)d_in[3];
    float* out = (float*)d_out;

    const int n = in_sizes[0] / NZ_COLS;           // 8192
    const int pack_smem = 128 * 133 * 4;           // ~68 KB

    cudaFuncSetAttribute(pack_b_kernel, cudaFuncAttributeMaxDynamicSharedMemorySize, pack_smem);
    cudaFuncSetAttribute(sv_mma_kernel, cudaFuncAttributeMaxDynamicSharedMemorySize, SMEM_MAIN);

    pack_b_kernel<<<130, 256, pack_smem>>>(w_sv, w_ss, w_vv);
    sv_mma_kernel<<<dim3(n / 128, 2), 256, SMEM_MAIN>>>(x, out);
}